// round 3
// baseline (speedup 1.0000x reference)
#include <cuda_runtime.h>
#include <cuda_bf16.h>

#define NROWS 4096
#define NF    256
#define NH    4
#define NB    64            // blocks (<= 148 SMs -> spin barrier is deadlock-free)
#define TPB   512
#define RPB   (NROWS / NB)  // 64 rows per block

// Scratch (__device__ globals per allocation-free rule)
__device__ float4  g_dpart[NB];          // per-block d[h] partials
__device__ float   g_cpart[NB * NF];     // per-block weighted column sums
__device__ unsigned g_cnt1, g_cnt2;      // monotonic epoch counters (graph-replay safe)

__device__ __forceinline__ void grid_sync(unsigned* cnt) {
    __threadfence();
    __syncthreads();
    if (threadIdx.x == 0) {
        unsigned old = atomicAdd(cnt, 1u);
        unsigned target = (old / NB + 1u) * NB;   // end of THIS launch's epoch
        while (*(volatile unsigned*)cnt < target) { }
        __threadfence();
    }
    __syncthreads();
}

__global__ void __launch_bounds__(TPB, 1)
fused_mha(const float* __restrict__ x, const float* __restrict__ W,
          float* __restrict__ out)
{
    __shared__ float4 w2s[NH][NF / 4];   // 4 KB: W2 = W[:, 256:512]
    __shared__ float  es[RPB][NH];       // exp(scores) for this block's 64 rows
    __shared__ float  dred[16][NH];      // per-warp d partials
    __shared__ float  sinv[NH];          // 1 / (H * d[h])
    __shared__ float  su[RPB];           // per-row combined weight u[j]
    __shared__ float  chalf[NF];         // half-block c_part staging
    __shared__ float  scf[NF];           // final broadcast row

    const int tid  = threadIdx.x;
    const int lane = tid & 31, warp = tid >> 5;
    const int b    = blockIdx.x;
    const int rowbase = b * RPB;

    // ---- W2 into smem (256 float4) -----------------------------------------
    if (tid < NH * (NF / 4)) {
        int h = tid >> 6, k = tid & 63;
        w2s[h][k] = reinterpret_cast<const float4*>(W + h * 2 * NF + NF)[k];
    }
    __syncthreads();

    // ---- Phase 1: scores + exp; x read straight from L2, 1 row per warp ----
    // (no max-subtraction: scores ~ N(0, 0.16); softmax is shift-invariant,
    //  so this matches the reference)
    float dw0 = 0.f, dw1 = 0.f, dw2 = 0.f, dw3 = 0.f;
    #pragma unroll
    for (int r = warp; r < RPB; r += 16) {
        const float4* xr = reinterpret_cast<const float4*>(x + (size_t)(rowbase + r) * NF);
        float a0 = 0.f, a1 = 0.f, a2 = 0.f, a3 = 0.f;
        #pragma unroll
        for (int t = 0; t < 2; ++t) {
            const int k4 = lane + t * 32;
            const float4 xv = xr[k4];
            float4 w;
            w = w2s[0][k4]; a0 += xv.x*w.x + xv.y*w.y + xv.z*w.z + xv.w*w.w;
            w = w2s[1][k4]; a1 += xv.x*w.x + xv.y*w.y + xv.z*w.z + xv.w*w.w;
            w = w2s[2][k4]; a2 += xv.x*w.x + xv.y*w.y + xv.z*w.z + xv.w*w.w;
            w = w2s[3][k4]; a3 += xv.x*w.x + xv.y*w.y + xv.z*w.z + xv.w*w.w;
        }
        #pragma unroll
        for (int o = 16; o; o >>= 1) {
            a0 += __shfl_xor_sync(0xffffffffu, a0, o);
            a1 += __shfl_xor_sync(0xffffffffu, a1, o);
            a2 += __shfl_xor_sync(0xffffffffu, a2, o);
            a3 += __shfl_xor_sync(0xffffffffu, a3, o);
        }
        if (lane == 0) {
            float e0 = expf(a0), e1 = expf(a1), e2 = expf(a2), e3 = expf(a3);
            es[r][0] = e0; es[r][1] = e1; es[r][2] = e2; es[r][3] = e3;
            dw0 += e0; dw1 += e1; dw2 += e2; dw3 += e3;
        }
    }
    if (lane == 0) { dred[warp][0] = dw0; dred[warp][1] = dw1;
                     dred[warp][2] = dw2; dred[warp][3] = dw3; }
    __syncthreads();
    if (tid < NH) {
        float s = 0.f;
        #pragma unroll
        for (int w = 0; w < 16; ++w) s += dred[w][tid];
        ((float*)&g_dpart[b])[tid] = s;
    }

    grid_sync(&g_cnt1);

    // ---- Phase 2: inv[h], per-row weight u, per-block c_part ---------------
    if (warp == 0) {
        float4 da = g_dpart[lane];
        float4 db = g_dpart[lane + 32];
        float s0 = da.x + db.x, s1 = da.y + db.y, s2 = da.z + db.z, s3 = da.w + db.w;
        #pragma unroll
        for (int o = 16; o; o >>= 1) {
            s0 += __shfl_xor_sync(0xffffffffu, s0, o);
            s1 += __shfl_xor_sync(0xffffffffu, s1, o);
            s2 += __shfl_xor_sync(0xffffffffu, s2, o);
            s3 += __shfl_xor_sync(0xffffffffu, s3, o);
        }
        if (lane == 0) {
            sinv[0] = 1.f / ((float)NH * s0);
            sinv[1] = 1.f / ((float)NH * s1);
            sinv[2] = 1.f / ((float)NH * s2);
            sinv[3] = 1.f / ((float)NH * s3);
        }
    }
    __syncthreads();
    if (tid < RPB)
        su[tid] = es[tid][0]*sinv[0] + es[tid][1]*sinv[1]
                + es[tid][2]*sinv[2] + es[tid][3]*sinv[3];
    __syncthreads();

    // c_part[f] = sum over this block's rows of u[j]*x[j,f]
    // thread t: column f = t&255, row half = t>>8 (32 rows each)
    {
        const int f = tid & (NF - 1);
        const int half = tid >> 8;
        const int rb = half * 32;
        float acc = 0.f;
        #pragma unroll 8
        for (int r = 0; r < 32; ++r)
            acc += su[rb + r] * x[(size_t)(rowbase + rb + r) * NF + f];
        if (half) chalf[f] = acc;
        __syncthreads();
        if (!half) g_cpart[b * NF + f] = acc + chalf[f];
    }

    grid_sync(&g_cnt2);

    // ---- Phase 3: every block reduces all c_parts (64x256 floats, 64 KB) ---
    if (tid < NF) {
        float c = 0.f;
        #pragma unroll 8
        for (int bb = 0; bb < NB; ++bb) c += g_cpart[bb * NF + tid];
        scf[tid] = (c > 0.f) ? c : 0.2f * c;     // leaky_relu(mean over heads)
    }
    __syncthreads();

    // broadcast to this block's 64 output rows (coalesced float4 stores)
    const float4 v = reinterpret_cast<const float4*>(scf)[tid & 63];
    float4* og = reinterpret_cast<float4*>(out) + (size_t)rowbase * (NF / 4);
    #pragma unroll
    for (int i = 0; i < (RPB * NF / 4) / TPB; ++i)   // 8 stores/thread
        og[tid + i * TPB] = v;
}

extern "C" void kernel_launch(void* const* d_in, const int* in_sizes, int n_in,
                              void* d_out, int out_size) {
    const float* x = (const float*)d_in[0];   // (4096, 256) f32
    const float* W = (const float*)d_in[1];   // (4, 512) f32; only W[:,256:] matters
    // d_in[2] = b: cancels inside softmax, mathematically irrelevant
    float* out = (float*)d_out;               // (4096, 256) f32

    fused_mha<<<NB, TPB>>>(x, W, out);
}

// round 4
// speedup vs baseline: 1.6115x; 1.6115x over previous
#include <cuda_runtime.h>
#include <cuda_bf16.h>

#define NROWS 4096
#define NF    256
#define NH    4
#define NB    128           // blocks (<= 148 SMs -> spin barrier is deadlock-free)
#define TPB   256
#define RPB   (NROWS / NB)  // 32 rows per block

// Scratch (__device__ globals per allocation-free rule)
__device__ float4  g_dpart[NB];          // per-block d[h] partials
__device__ float   g_cpart[NB * NF];     // per-block head-collapsed column sums
__device__ float   g_cf[NF];             // final broadcast row
__device__ unsigned g_cnt1, g_cnt2;      // monotonic epoch counters (graph-replay safe)

__device__ __forceinline__ void grid_sync(unsigned* cnt) {
    __threadfence();
    __syncthreads();
    if (threadIdx.x == 0) {
        unsigned old = atomicAdd(cnt, 1u);
        unsigned target = (old / NB + 1u) * NB;   // end of THIS launch's epoch
        while (*(volatile unsigned*)cnt < target) { }
        __threadfence();
    }
    __syncthreads();
}

__global__ void __launch_bounds__(TPB, 1)
fused_mha(const float* __restrict__ x, const float* __restrict__ W,
          float* __restrict__ out)
{
    __shared__ float4 xs[RPB * (NF / 4)];   // 32 KB: this block's 32 rows of x
    __shared__ float4 w2s[NH][NF / 4];      // 4 KB:  W2 = W[:, 256:512]
    __shared__ float4 es4[RPB];             // exp(scores) per row, packed
    __shared__ float  sinv[NH];             // 1 / (H * d[h])
    __shared__ float  sred[8];              // phase-2 per-warp partials

    const int tid  = threadIdx.x;
    const int lane = tid & 31, warp = tid >> 5;
    const int b    = blockIdx.x;
    const int rowbase = b * RPB;

    // ---- load W2 + x tile (coalesced, x read from DRAM exactly once) -------
    if (tid < NH * (NF / 4)) {
        int h = tid >> 6, k = tid & 63;
        w2s[h][k] = reinterpret_cast<const float4*>(W + h * 2 * NF + NF)[k];
    }
    const float4* xg = reinterpret_cast<const float4*>(x) + (size_t)rowbase * (NF / 4);
    #pragma unroll
    for (int i = 0; i < (RPB * NF / 4) / TPB; ++i)   // 8 float4 loads/thread
        xs[tid + i * TPB] = xg[tid + i * TPB];
    __syncthreads();

    // ---- Phase 1a: scores + exp, 4 rows per warp ---------------------------
    // (no max-subtraction: scores ~ N(0, 0.16); softmax is shift-invariant,
    //  so this matches the reference)
    #pragma unroll
    for (int r = warp; r < RPB; r += 8) {
        float a0 = 0.f, a1 = 0.f, a2 = 0.f, a3 = 0.f;
        #pragma unroll
        for (int t = 0; t < 2; ++t) {
            const int k4 = lane + t * 32;
            const float4 xv = xs[r * (NF / 4) + k4];
            float4 w;
            w = w2s[0][k4]; a0 += xv.x*w.x + xv.y*w.y + xv.z*w.z + xv.w*w.w;
            w = w2s[1][k4]; a1 += xv.x*w.x + xv.y*w.y + xv.z*w.z + xv.w*w.w;
            w = w2s[2][k4]; a2 += xv.x*w.x + xv.y*w.y + xv.z*w.z + xv.w*w.w;
            w = w2s[3][k4]; a3 += xv.x*w.x + xv.y*w.y + xv.z*w.z + xv.w*w.w;
        }
        #pragma unroll
        for (int o = 16; o; o >>= 1) {
            a0 += __shfl_xor_sync(0xffffffffu, a0, o);
            a1 += __shfl_xor_sync(0xffffffffu, a1, o);
            a2 += __shfl_xor_sync(0xffffffffu, a2, o);
            a3 += __shfl_xor_sync(0xffffffffu, a3, o);
        }
        if (lane == 0)
            es4[r] = make_float4(expf(a0), expf(a1), expf(a2), expf(a3));
    }
    __syncthreads();

    // ---- Phase 1b: per-block d[h] partial + register-resident t[h, f=tid] --
    if (tid < NH) {
        float s = 0.f;
        #pragma unroll
        for (int r = 0; r < RPB; ++r) s += ((const float*)&es4[r])[tid];
        ((float*)&g_dpart[b])[tid] = s;
    }
    float t0 = 0.f, t1 = 0.f, t2 = 0.f, t3 = 0.f;
    {
        const float* xsf = (const float*)xs;
        #pragma unroll
        for (int r = 0; r < RPB; ++r) {
            const float4 e = es4[r];                 // smem broadcast
            const float xv = xsf[r * NF + tid];      // conflict-free
            t0 += e.x * xv; t1 += e.y * xv;
            t2 += e.z * xv; t3 += e.w * xv;
        }
    }

    grid_sync(&g_cnt1);

    // ---- Phase 2: global inv[h]; head-collapse; distributed column reduce --
    if (warp == 0) {
        float4 d0 = g_dpart[lane];
        float4 d1 = g_dpart[lane + 32];
        float4 d2 = g_dpart[lane + 64];
        float4 d3 = g_dpart[lane + 96];
        float s0 = (d0.x + d1.x) + (d2.x + d3.x);
        float s1 = (d0.y + d1.y) + (d2.y + d3.y);
        float s2 = (d0.z + d1.z) + (d2.z + d3.z);
        float s3 = (d0.w + d1.w) + (d2.w + d3.w);
        #pragma unroll
        for (int o = 16; o; o >>= 1) {
            s0 += __shfl_xor_sync(0xffffffffu, s0, o);
            s1 += __shfl_xor_sync(0xffffffffu, s1, o);
            s2 += __shfl_xor_sync(0xffffffffu, s2, o);
            s3 += __shfl_xor_sync(0xffffffffu, s3, o);
        }
        if (lane == 0) {
            sinv[0] = 1.f / ((float)NH * s0);
            sinv[1] = 1.f / ((float)NH * s1);
            sinv[2] = 1.f / ((float)NH * s2);
            sinv[3] = 1.f / ((float)NH * s3);
        }
    }
    __syncthreads();

    // head-collapsed partial for column f = tid (4 FMAs; no second x pass)
    g_cpart[b * NF + tid] = sinv[0]*t0 + sinv[1]*t1 + sinv[2]*t2 + sinv[3]*t3;

    grid_sync(&g_cnt2);

    // distributed final reduce: block b owns columns 2b and 2b+1
    {
        const int col = tid >> 7;              // 0 or 1
        const int bb  = tid & 127;             // source block
        const int f   = 2 * b + col;
        float v = g_cpart[bb * NF + f];
        #pragma unroll
        for (int o = 16; o; o >>= 1) v += __shfl_xor_sync(0xffffffffu, v, o);
        if (lane == 0) sred[warp] = v;
        __syncthreads();
        if (tid < 2) {
            float c = (sred[tid*4+0] + sred[tid*4+1]) + (sred[tid*4+2] + sred[tid*4+3]);
            g_cf[2 * b + tid] = (c > 0.f) ? c : 0.2f * c;   // leaky_relu
        }
    }

    grid_sync(&g_cnt1);   // epoch arithmetic makes counter reuse safe

    // ---- Phase 3: broadcast final row to this block's 32 output rows -------
    const float4 v = reinterpret_cast<const float4*>(g_cf)[tid & 63];
    float4* og = reinterpret_cast<float4*>(out) + (size_t)rowbase * (NF / 4);
    #pragma unroll
    for (int i = 0; i < (RPB * NF / 4) / TPB; ++i)   // 8 float4 stores/thread
        og[tid + i * TPB] = v;
}

extern "C" void kernel_launch(void* const* d_in, const int* in_sizes, int n_in,
                              void* d_out, int out_size) {
    const float* x = (const float*)d_in[0];   // (4096, 256) f32
    const float* W = (const float*)d_in[1];   // (4, 512) f32; only W[:,256:] matters
    // d_in[2] = b: cancels inside softmax, mathematically irrelevant
    float* out = (float*)d_out;               // (4096, 256) f32

    fused_mha<<<NB, TPB>>>(x, W, out);
}